// round 10
// baseline (speedup 1.0000x reference)
#include <cuda_runtime.h>
#include <cstdint>

// HexPool: out[i, :] = max_{k<7} x[neigh_indices[i,k], :]
// x: (655362, 64) f32 ; neigh_indices: (163842, 7) int32 ; out: (163842, 64) f32
//
// Geometry: 8 threads (quarter-warp) per row, ONE 256-bit load (LDG.256,
// ld.global.nc.L2::evict_last.v8.b32) per gather per thread -> half the load
// instructions of the 16-thread/row LDG.128 version, same coalescing (each
// warp instruction reads 4 rows x 256B contiguous). evict_last pins the hot
// 42MB x region in L2 (sm_103a only allows this policy on 256-bit loads).
// Output stores stay __stcs (evict-first), the R7 -10% win.
//
// grid = ceil(163842/32) = 5121; tail clamps row + predicates store; all
// lanes stay converged through every __shfl_sync.

#define N_OUT 163842
#define KNB   7
#define VEC_PER_ROW 16      // 64 floats / 4
#define BLOCK_THREADS 256
#define ROWS_PER_BLOCK 32   // 256 threads / 8 threads per row

struct f32x8 { float a0,a1,a2,a3,a4,a5,a6,a7; };

__device__ __forceinline__ f32x8 ldg256_evict_last(const void* p) {
    f32x8 v;
    asm volatile("ld.global.nc.L2::evict_last.v8.b32 "
                 "{%0,%1,%2,%3,%4,%5,%6,%7}, [%8];"
                 : "=f"(v.a0), "=f"(v.a1), "=f"(v.a2), "=f"(v.a3),
                   "=f"(v.a4), "=f"(v.a5), "=f"(v.a6), "=f"(v.a7)
                 : "l"(p));
    return v;
}

__global__ __launch_bounds__(BLOCK_THREADS) void hexpool_kernel(
    const float* __restrict__ x,           // [n_in][64] floats
    const int* __restrict__ idx,           // [N_OUT][7] int32
    float4* __restrict__ out)               // [N_OUT][16] float4
{
    const int tid = blockIdx.x * BLOCK_THREADS + threadIdx.x;
    const int row_raw = tid >> 3;                    // 8 threads per row
    const int row = row_raw < N_OUT ? row_raw : (N_OUT - 1);
    const int col8 = tid & 7;                        // which 8-float chunk (0..7)

    const int lane = threadIdx.x & 31;
    const int q_base = lane & 24;                    // quarter-warp start lane
    const int sub = lane & 7;

    // Lanes sub<7 of each quarter-warp load the 7 indices for this row.
    int my_idx = 0;
    if (sub < KNB) {
        my_idx = __ldg(&idx[row * KNB + sub]);
    }

    const float NEG = -3.402823466e+38f;
    f32x8 m = { NEG, NEG, NEG, NEG, NEG, NEG, NEG, NEG };

    #pragma unroll
    for (int k = 0; k < KNB; ++k) {
        int j = __shfl_sync(0xFFFFFFFFu, my_idx, q_base + k);
        const float* p = x + (long long)j * 64 + col8 * 8;
        f32x8 v = ldg256_evict_last(p);
        m.a0 = fmaxf(m.a0, v.a0);  m.a1 = fmaxf(m.a1, v.a1);
        m.a2 = fmaxf(m.a2, v.a2);  m.a3 = fmaxf(m.a3, v.a3);
        m.a4 = fmaxf(m.a4, v.a4);  m.a5 = fmaxf(m.a5, v.a5);
        m.a6 = fmaxf(m.a6, v.a6);  m.a7 = fmaxf(m.a7, v.a7);
    }

    if (row_raw < N_OUT) {
        float4* orow = &out[(long long)row_raw * VEC_PER_ROW];
        float4 lo = make_float4(m.a0, m.a1, m.a2, m.a3);
        float4 hi = make_float4(m.a4, m.a5, m.a6, m.a7);
        __stcs(orow + col8 * 2,     lo);   // evict-first output
        __stcs(orow + col8 * 2 + 1, hi);
    }
}

extern "C" void kernel_launch(void* const* d_in, const int* in_sizes, int n_in,
                              void* d_out, int out_size)
{
    const float* x   = (const float*)d_in[0];
    const int*   idx = (const int*)d_in[1];
    float4*      out = (float4*)d_out;

    const int grid = (N_OUT + ROWS_PER_BLOCK - 1) / ROWS_PER_BLOCK;  // 5121
    hexpool_kernel<<<grid, BLOCK_THREADS>>>(x, idx, out);
}

// round 11
// speedup vs baseline: 1.0784x; 1.0784x over previous
#include <cuda_runtime.h>
#include <cstdint>

// HexPool: out[i, :] = max_{k<7} x[neigh_indices[i,k], :]
// x: (655362, 64) f32 ; neigh_indices: (163842, 7) int32 ; out: (163842, 64) f32
//
// Best measured transport shape (R7, 22.1us): 16 threads (half-warp) per row,
// one LDG.128 per gather -> each warp instruction touches only 2 distinct rows
// (8-thread/row variants lost ~1-2us in three separate A/Bs). Output stores
// __stcs (evict-first): -10% (R7). This round adds the R10-confirmed DRAM
// reduction (evict_last on x, DRAM 31%->25.5%) to the good geometry via the
// createpolicy + ld.global.nc.L2::cache_hint path, which unlike the inline
// .L2::evict_last modifier is legal on 128-bit loads.

#define N_OUT 163842
#define KNB   7
#define VEC_PER_ROW 16   // 64 floats / 4

__device__ __forceinline__ float4 ldg_evict_last_128(const float4* p, uint64_t pol) {
    float4 v;
    asm volatile("ld.global.nc.L2::cache_hint.v4.f32 {%0,%1,%2,%3}, [%4], %5;"
                 : "=f"(v.x), "=f"(v.y), "=f"(v.z), "=f"(v.w)
                 : "l"(p), "l"(pol));
    return v;
}

__global__ __launch_bounds__(256) void hexpool_kernel(
    const float4* __restrict__ x,          // viewed as [n_in][16] float4
    const int* __restrict__ idx,           // [N_OUT][7] int32
    float4* __restrict__ out)               // [N_OUT][16] float4
{
    const int gid = blockIdx.x * blockDim.x + threadIdx.x;
    const int row_raw = gid >> 4;                 // output row (may overshoot in tail)
    const int row = row_raw < N_OUT ? row_raw : (N_OUT - 1);
    const int col = gid & 15;                     // float4 column within row

    const int lane = threadIdx.x & 31;
    const int half_base = lane & 16;              // 0 or 16: start lane of my half-warp
    const int sub = lane & 15;

    // L2 policy: keep x's lines resident (evict_last).
    uint64_t pol;
    asm volatile("createpolicy.fractional.L2::evict_last.b64 %0, 1.0;" : "=l"(pol));

    // Lanes sub<7 of each half-warp load the 7 indices for this half-warp's row.
    int my_idx = 0;
    if (sub < KNB) {
        my_idx = __ldg(&idx[row * KNB + sub]);
    }

    float4 m = make_float4(-3.402823466e+38f, -3.402823466e+38f,
                           -3.402823466e+38f, -3.402823466e+38f);

    #pragma unroll
    for (int k = 0; k < KNB; ++k) {
        int j = __shfl_sync(0xFFFFFFFFu, my_idx, half_base + k);
        float4 v = ldg_evict_last_128(&x[(long long)j * VEC_PER_ROW + col], pol);
        m.x = fmaxf(m.x, v.x);
        m.y = fmaxf(m.y, v.y);
        m.z = fmaxf(m.z, v.z);
        m.w = fmaxf(m.w, v.w);
    }

    if (row_raw < N_OUT) {
        __stcs(&out[gid], m);   // evict-first: don't displace x's L2 lines
    }
}

extern "C" void kernel_launch(void* const* d_in, const int* in_sizes, int n_in,
                              void* d_out, int out_size)
{
    const float4* x   = (const float4*)d_in[0];
    const int*    idx = (const int*)d_in[1];
    float4*       out = (float4*)d_out;

    const int total_threads = N_OUT * VEC_PER_ROW;   // 2,621,472
    const int block = 256;
    const int grid  = (total_threads + block - 1) / block;
    hexpool_kernel<<<grid, block>>>(x, idx, out);
}